// round 15
// baseline (speedup 1.0000x reference)
#include <cuda_runtime.h>
#include <cuda_bf16.h>

// WaveletTransformLayer: x (B=128, T=2048, F=32) f32.
// Per (b,f): d1 (2047) | d2 (2044) | d3 (2037) | ma3 (2037), each / T.
//   m2[t] = 8*ma2[t] = x[t] + 2(x[t+1]+x[t+2]+x[t+3]) + x[t+4]
//   S[t]  = 64*ma3[t] = sum_{j=0..7} m2[t+j]
//   d1[t] = (x[t+1]-x[t])/2 ; d2[t] = (x[t+3]+x[t+4])/2 - m2[t]/8
//   d3[t] = m2[t+7]/8 - S[t]/64 ; ma3[t] = S[t]/64
//
// R15: sliding-window compute, staging transpose.
//  Compute: warp = 8-t strip, lane = f. Coalesced direct LDG (19/thread),
//  FIR in registers (zero redundant smem reads). Stage via smem (pitch 33,
//  conflict-free both ways). Store: warp = (stream, t-quarter), lane = t,
//  coalesced STG. Geometry: 512 thr, 3 blocks/SM, persistent grid 444.

#define T_LEN   2048
#define F_DIM   32
#define TT      128
#define NTILES  (T_LEN / TT)      // 16
#define NUNITS  (NTILES * 128)    // 2048
#define OUT_PER_F 8165
#define SEG1    2047
#define SEG2    4091
#define SEG3    6128
#define LIM1    2047
#define LIM2    2044
#define LIM3    2037

#define NSM     148
#define BLKSM   3
#define GRID    (NSM * BLKSM)     // 444
#define NTHR    512
#define SPITCH  33
#define SSEG    (TT * SPITCH)     // 4224 floats per stream
#define SMEM_BYTES (4 * SSEG * 4) // 67584 B

__global__ __launch_bounds__(NTHR, BLKSM)
void wavelet_kernel(const float* __restrict__ x, float* __restrict__ out) {
    extern __shared__ float st[];     // stage[stream][t 0..127][f], pitch 33

    const int tid = threadIdx.x;      // 0..511
    const int w   = tid >> 5;         // warp 0..15
    const int l   = tid & 31;

    // compute-phase ids: warp w owns t-strip [8w, 8w+8), lane = feature
    const int ts = w << 3;

    // store-phase ids: warp -> (stream s, t-quarter tq), lane = t
    const int s    = w >> 2;
    const int tq   = (w & 3) << 5;
    const int seg  = (s == 0) ? 0 : (s == 1) ? SEG1 : (s == 2) ? SEG2 : SEG3;
    const int lim  = (s == 0) ? LIM1 : (s == 1) ? LIM2 : LIM3;

    const float inv   = 1.0f / 2048.0f;
    const float inv2  = inv * 0.5f;
    const float inv8  = inv * 0.125f;
    const float inv64 = inv * 0.015625f;

    for (int u = blockIdx.x; u < NUNITS; u += GRID) {
        const int tile = u & (NTILES - 1);
        const int b    = u >> 4;
        const int t0   = tile * TT;
        const float* base = x + (size_t)b * (T_LEN * F_DIM);

        // ---- Compute phase: 19 coalesced LDG per lane, FIR in registers ----
        float xv[19];
        if (tile != NTILES - 1) {
            const float* p = base + (size_t)(t0 + ts) * F_DIM + l;
            #pragma unroll
            for (int j = 0; j < 19; ++j) xv[j] = p[F_DIM * j];
        } else {
            #pragma unroll
            for (int j = 0; j < 19; ++j) {
                int tt = t0 + ts + j; if (tt > T_LEN - 1) tt = T_LEN - 1;  // clamp
                xv[j] = base[(size_t)tt * F_DIM + l];
            }
        }

        float m2[15];
        #pragma unroll
        for (int i = 0; i < 15; ++i)
            m2[i] = (xv[i] + xv[i + 4]) + 2.0f * ((xv[i + 1] + xv[i + 2]) + xv[i + 3]);

        float S = ((m2[0] + m2[1]) + (m2[2] + m2[3]))
                + ((m2[4] + m2[5]) + (m2[6] + m2[7]));

        float* srow = st + ts * SPITCH + l;    // stream 0, t=ts, f=l
        #pragma unroll
        for (int k = 0; k < 8; ++k) {
            float d1 = (xv[k + 1] - xv[k]) * inv2;
            float d2 = (xv[k + 3] + xv[k + 4]) * inv2 - m2[k] * inv8;
            float d3 = m2[k + 7] * inv8 - S * inv64;
            float m3 = S * inv64;
            float* q = srow + k * SPITCH;      // lanes consecutive: conflict-free
            q[0]        = d1;
            q[SSEG]     = d2;
            q[2 * SSEG] = d3;
            q[3 * SSEG] = m3;
            if (k < 7) S += m2[k + 8] - m2[k];
        }
        __syncthreads();

        // ---- Store phase: warp = (stream, t-quarter), lane = t, loop f ----
        const float* sp = st + (size_t)s * SSEG + (tq + l) * SPITCH;  // stride 33: CF
        float* op = out + (size_t)b * (F_DIM * OUT_PER_F) + seg + t0 + tq + l;
        if (tile != NTILES - 1) {
            #pragma unroll 8
            for (int f = 0; f < F_DIM; ++f)
                op[(size_t)f * OUT_PER_F] = sp[f];
        } else {
            if (t0 + tq + l < lim) {
                #pragma unroll 8
                for (int f = 0; f < F_DIM; ++f)
                    op[(size_t)f * OUT_PER_F] = sp[f];
            }
        }
        __syncthreads();   // staging reused next iteration
    }
}

extern "C" void kernel_launch(void* const* d_in, const int* in_sizes, int n_in,
                              void* d_out, int out_size) {
    const float* x = (const float*)d_in[0];
    float* out = (float*)d_out;
    cudaFuncSetAttribute(wavelet_kernel,
                         cudaFuncAttributeMaxDynamicSharedMemorySize, SMEM_BYTES);
    wavelet_kernel<<<GRID, NTHR, SMEM_BYTES>>>(x, out);
}